// round 12
// baseline (speedup 1.0000x reference)
#include <cuda_runtime.h>
#include <math.h>

#define B_   128
#define L_   64
#define D_   256
#define H_   512
#define AS_  512
#define AP_  256
#define G3H_ 1536
#define NEGV (-1.0e9f)
#define NB   128
#define NT_  512
#define NU   4
#define NSLOT (NB*NU)
#define GSTRIDE (NB*NT_)

// smem per unit: Abuf 2*32*32 ull = 16384B, Bbuf 2*32*68 f = 17408B, scr 2304B
#define SMEM_ASD   0
#define SMEM_BS    65536
#define SMEM_SCR   135168
#define SMEM_TOTAL 144384

// ---------------- scratch ----------------
__device__ float g_dense   [B_*L_*D_];
__device__ float g_enc_gi  [B_*L_*G3H_];
__device__ float g_decx_gi [B_*L_*G3H_];
__device__ float g_enc_out [B_*L_*H_];
__device__ float g_enc_keys[B_*L_*AS_];
__device__ float g_ptr_keys[B_*L_*AP_];
__device__ float g_h    [B_*H_];
__device__ float g_gh   [B_*G3H_];
__device__ float g_gh2  [B_*G3H_];
__device__ float g_gh3  [B_*G3H_];
__device__ float g_gh4  [B_*G3H_];
__device__ float g_gic  [B_*G3H_];
__device__ float g_gic2 [B_*G3H_];
__device__ float g_gic3 [B_*G3H_];
__device__ float g_gic4 [B_*G3H_];
__device__ float g_ctx  [B_*H_];
__device__ float g_q    [B_*AS_];
__device__ float g_q2   [B_*AS_];
__device__ float g_q3   [B_*AS_];
__device__ float g_q4   [B_*AS_];
__device__ float g_dout [B_*D_];
__device__ float g_dout2[B_*D_];
__device__ float g_dout3[B_*D_];
__device__ float g_dout4[B_*D_];
__device__ float g_pq   [B_*AP_];
__device__ float g_pq2  [B_*AP_];
// transposed (k-major) weight copies
__device__ float g_encWiT   [D_*G3H_];
__device__ float g_decWiXT  [D_*G3H_];
__device__ float g_encWhT   [H_*G3H_];
__device__ float g_decWhT   [H_*G3H_];
__device__ float g_decWiCtxT[H_*G3H_];
__device__ float g_WoutT    [H_*D_];
__device__ int   g_idx  [L_*B_];
__device__ int   g_fo   [B_*L_];
__device__ unsigned long long g_cnt;

typedef unsigned long long ull;
__device__ __forceinline__ ull pk2(float x, float y) {
    ull r; asm("mov.b64 %0, {%1, %2};" : "=l"(r) : "f"(x), "f"(y)); return r;
}
__device__ __forceinline__ void upk2(ull v, float& x, float& y) {
    asm("mov.b64 {%0, %1}, %2;" : "=f"(x), "=f"(y) : "l"(v));
}
__device__ __forceinline__ ull fma2(ull a, ull b, ull c) {
    ull d; asm("fma.rn.f32x2 %0, %1, %2, %3;" : "=l"(d) : "l"(a), "l"(b), "l"(c));
    return d;
}
__device__ __forceinline__ float tanhax(float x) {
    float y; asm("tanh.approx.f32 %0, %1;" : "=f"(y) : "f"(x)); return y;
}
__device__ __forceinline__ float ex2ax(float x) {
    float y; asm("ex2.approx.f32 %0, %1;" : "=f"(y) : "f"(x)); return y;
}
__device__ __forceinline__ float expax(float x) { return ex2ax(x * 1.4426950408889634f); }
__device__ __forceinline__ float sigax(float x) { return 0.5f * tanhax(0.5f * x) + 0.5f; }

__device__ __forceinline__ void bar_u(int u) {
    asm volatile("bar.sync %0, 128;" :: "r"(1 + u) : "memory");
}
__device__ __forceinline__ void cp16(unsigned dst, const float* src) {
    asm volatile("cp.async.cg.shared.global [%0], [%1], 16;" :: "r"(dst), "l"(src) : "memory");
}
__device__ __forceinline__ void cp_commit() {
    asm volatile("cp.async.commit_group;" ::: "memory");
}
__device__ __forceinline__ void cp_wait0() {
    asm volatile("cp.async.wait_group 0;" ::: "memory");
}
__device__ __forceinline__ unsigned smem_u32(const void* p) {
    unsigned a;
    asm("{ .reg .u64 t; cvta.to.shared.u64 t, %1; cvt.u32.u64 %0, t; }" : "=r"(a) : "l"(p));
    return a;
}

__device__ __forceinline__ void gsync() {
    __syncthreads();
    if (threadIdx.x == 0) {
        ull* p = &g_cnt;
        ull old;
        asm volatile("atom.add.release.gpu.u64 %0, [%1], %2;"
                     : "=l"(old) : "l"(p), "l"(1ULL) : "memory");
        ull target = (old - (old & (ull)(NB - 1))) + NB;
        ull cur;
        do {
            asm volatile("ld.acquire.gpu.u64 %0, [%1];" : "=l"(cur) : "l"(p) : "memory");
        } while (cur < target);
    }
    __syncthreads();
}

// ---------------- cp.async double-buffered 32x64 tile GEMM, BK=32 ----------------
// C[m0:+32,n0:+64] = (sum of NA A-arrays)[m0:+32, kb:ke] * B (+bias)
// B layout (k-major): B(k,n) = Bm[k*ldb + n]. One bar.sync per 32-k slice.
template<int NA>
__device__ __forceinline__ void tileg(
    const float* __restrict__ A0, const float* __restrict__ A1,
    const float* __restrict__ A2p, const float* __restrict__ A3p, int lda,
    const float* __restrict__ Bm, int ldb,
    const float* __restrict__ bias,
    float* __restrict__ C, int ldc, int kb, int ke,
    int m0, int n0, int t, int u,
    ull (*Asd)[32][32], float (*Bs)[32][68], unsigned bs_u32)
{
    const int ar = t >> 2, ac = t & 3;
    const int tr4 = (t >> 4) << 2;
    const int tc4 = (t & 15) << 2;
    const int arow = (m0 + ar) * lda;
    // B chunk coords: 4 chunks of 16B per thread (512 chunks = 32kk x 16q)
    const int kk0 = t >> 4,          q0 = t & 15;
    const int kk1 = (t + 128) >> 4,  q1 = (t + 128) & 15;
    const int kk2 = (t + 256) >> 4,  q2 = (t + 256) & 15;
    const int kk3 = (t + 384) >> 4,  q3 = (t + 384) & 15;
    const unsigned bdst0 = bs_u32 + kk0 * 272 + q0 * 16;
    const unsigned bdst1 = bs_u32 + kk1 * 272 + q1 * 16;
    const unsigned bdst2 = bs_u32 + kk2 * 272 + q2 * 16;
    const unsigned bdst3 = bs_u32 + kk3 * 272 + q3 * 16;

    ull acc00=0,acc01=0,acc10=0,acc11=0,acc20=0,acc21=0,acc30=0,acc31=0;
    float4 va0, va1;

    auto ldA = [&](int k0) {
        va0 = *(const float4*)(A0 + arow + k0 + ac*4);
        va1 = *(const float4*)(A0 + arow + k0 + 16 + ac*4);
        if (NA > 1) {
            float4 x = *(const float4*)(A1 + arow + k0 + ac*4);
            float4 y = *(const float4*)(A1 + arow + k0 + 16 + ac*4);
            va0.x+=x.x; va0.y+=x.y; va0.z+=x.z; va0.w+=x.w;
            va1.x+=y.x; va1.y+=y.y; va1.z+=y.z; va1.w+=y.w;
        }
        if (NA > 2) {
            float4 x = *(const float4*)(A2p + arow + k0 + ac*4);
            float4 y = *(const float4*)(A2p + arow + k0 + 16 + ac*4);
            va0.x+=x.x; va0.y+=x.y; va0.z+=x.z; va0.w+=x.w;
            va1.x+=y.x; va1.y+=y.y; va1.z+=y.z; va1.w+=y.w;
            x = *(const float4*)(A3p + arow + k0 + ac*4);
            y = *(const float4*)(A3p + arow + k0 + 16 + ac*4);
            va0.x+=x.x; va0.y+=x.y; va0.z+=x.z; va0.w+=x.w;
            va1.x+=y.x; va1.y+=y.y; va1.z+=y.z; va1.w+=y.w;
        }
    };
    auto cpB = [&](int k0, int p) {
        const unsigned po = p * 8704;
        cp16(bdst0 + po, Bm + (k0 + kk0)*ldb + n0 + q0*4);
        cp16(bdst1 + po, Bm + (k0 + kk1)*ldb + n0 + q1*4);
        cp16(bdst2 + po, Bm + (k0 + kk2)*ldb + n0 + q2*4);
        cp16(bdst3 + po, Bm + (k0 + kk3)*ldb + n0 + q3*4);
        cp_commit();
    };

    const int nit = (ke - kb) >> 5;
    ldA(kb);
    cpB(kb, 0);
    for (int it = 0; it < nit; it++) {
        const int p = it & 1;
        // stage A(it) into buf p (readers of buf p fenced by bar of it-1)
        Asd[p][ac*4+0][ar] = pk2(va0.x, va0.x);
        Asd[p][ac*4+1][ar] = pk2(va0.y, va0.y);
        Asd[p][ac*4+2][ar] = pk2(va0.z, va0.z);
        Asd[p][ac*4+3][ar] = pk2(va0.w, va0.w);
        Asd[p][16+ac*4+0][ar] = pk2(va1.x, va1.x);
        Asd[p][16+ac*4+1][ar] = pk2(va1.y, va1.y);
        Asd[p][16+ac*4+2][ar] = pk2(va1.z, va1.z);
        Asd[p][16+ac*4+3][ar] = pk2(va1.w, va1.w);
        cp_wait0();               // B buf p complete
        bar_u(u);
        if (it + 1 < nit) {
            ldA(kb + (it+1)*32);
            cpB(kb + (it+1)*32, 1 - p);
        }
#pragma unroll
        for (int kk = 0; kk < 32; kk++) {
            ulonglong2 a01 = *(const ulonglong2*)&Asd[p][kk][tr4];
            ulonglong2 a23 = *(const ulonglong2*)&Asd[p][kk][tr4+2];
            ulonglong2 bb  = *(const ulonglong2*)&Bs[p][kk][tc4];  // {b01, b23}
            acc00 = fma2(a01.x, bb.x, acc00); acc01 = fma2(a01.x, bb.y, acc01);
            acc10 = fma2(a01.y, bb.x, acc10); acc11 = fma2(a01.y, bb.y, acc11);
            acc20 = fma2(a23.x, bb.x, acc20); acc21 = fma2(a23.x, bb.y, acc21);
            acc30 = fma2(a23.y, bb.x, acc30); acc31 = fma2(a23.y, bb.y, acc31);
        }
    }
    bar_u(u);   // protect buffers for the unit's next tileg call

    float bx0=0.f, bx1=0.f, bx2=0.f, bx3=0.f;
    if (bias) { bx0=bias[n0+tc4]; bx1=bias[n0+tc4+1]; bx2=bias[n0+tc4+2]; bx3=bias[n0+tc4+3]; }
    ull accs[4][2] = {{acc00,acc01},{acc10,acc11},{acc20,acc21},{acc30,acc31}};
#pragma unroll
    for (int i = 0; i < 4; i++) {
        float x0,x1,x2,x3;
        upk2(accs[i][0], x0, x1); upk2(accs[i][1], x2, x3);
        float4 o; o.x=x0+bx0; o.y=x1+bx1; o.z=x2+bx2; o.w=x3+bx3;
        *(float4*)(C + (m0 + tr4 + i)*ldc + n0 + tc4) = o;
    }
}

// ---------------- attention jobs (fp32 tanh — argmax-safe) ----------------
__device__ __forceinline__ void attn_s2s_job(
    int b, int t, int t128, int u, float* scr,
    const int* __restrict__ lengths, const float* __restrict__ v)
{
    const int w = t128 >> 5, lane = t128 & 31;
    const int len = lengths[b];
    float* qs = scr + 64;
#pragma unroll
    for (int r = 0; r < 4; r++) {
        int a = t128 + r*128;
        qs[a] = g_q[b*AS_+a] + g_q2[b*AS_+a] + g_q3[b*AS_+a] + g_q4[b*AS_+a];
    }
    bar_u(u);
    const float* kb = g_enc_keys + b * L_ * AS_;
#pragma unroll
    for (int l = w; l < L_; l += 4) {
        const float* kp = kb + l * AS_;
        float acc = 0.f;
#pragma unroll 4
        for (int a = lane; a < AS_; a += 32)
            acc += tanhax(qs[a] + kp[a]) * v[a];
        for (int o = 16; o; o >>= 1) acc += __shfl_down_sync(0xffffffffu, acc, o);
        if (lane == 0) scr[l] = (t < len && l < len) ? acc : NEGV;
    }
    bar_u(u);
    if (w == 0) {
        float v0 = scr[lane], v1 = scr[lane+32];
        float m = fmaxf(v0, v1);
        for (int o = 16; o; o >>= 1) m = fmaxf(m, __shfl_xor_sync(0xffffffffu, m, o));
        float e0 = expax(v0-m), e1 = expax(v1-m);
        float s = e0 + e1;
        for (int o = 16; o; o >>= 1) s += __shfl_xor_sync(0xffffffffu, s, o);
        float inv = 1.f / s;
        scr[lane] = e0*inv; scr[lane+32] = e1*inv;
    }
    bar_u(u);
#pragma unroll
    for (int r = 0; r < 4; r++) {
        int j = t128 + r*128;
        float c = 0.f;
#pragma unroll 8
        for (int l = 0; l < L_; l++)
            c += scr[l] * g_enc_out[(b*L_+l)*H_ + j];
        g_ctx[b*H_ + j] = c;
    }
}

__device__ __forceinline__ void ptr_attn_job(
    int b, int tt, int t128, int u, float* scr,
    const int* __restrict__ lengths, const float* __restrict__ pv,
    float* __restrict__ out_logits, float* __restrict__ out_preds)
{
    const int w = t128 >> 5, lane = t128 & 31;
    const int len = lengths[b];
    float* qs = scr + 64;
#pragma unroll
    for (int r = 0; r < 2; r++) {
        int a = t128 + r*128;
        qs[a] = g_pq[b*AP_+a] + g_pq2[b*AP_+a];
    }
    bar_u(u);
    const float* kb = g_ptr_keys + b * L_ * AP_;
#pragma unroll
    for (int l = w; l < L_; l += 4) {
        const float* kp = kb + l * AP_;
        float acc = 0.f;
#pragma unroll 4
        for (int a = lane; a < AP_; a += 32)
            acc += tanhax(qs[a] + kp[a]) * pv[a];
        for (int o = 16; o; o >>= 1) acc += __shfl_down_sync(0xffffffffu, acc, o);
        if (lane == 0) {
            bool ok = (tt < len) && (l < len) && (g_fo[b*L_+l] >= tt);
            float val = ok ? acc : NEGV;
            scr[l] = val;
            out_logits[(b*L_+tt)*L_ + l] = val;
        }
    }
    bar_u(u);
    if (w == 0 && out_preds) {
        float v0 = scr[lane], v1 = scr[lane+32];
        float bv; int bidx;
        if (v1 > v0) { bv = v1; bidx = lane+32; } else { bv = v0; bidx = lane; }
        for (int o = 16; o; o >>= 1) {
            float ov = __shfl_down_sync(0xffffffffu, bv, o);
            int   oi = __shfl_down_sync(0xffffffffu, bidx, o);
            if (ov > bv || (ov == bv && oi < bidx)) { bv = ov; bidx = oi; }
        }
        if (lane == 0) out_preds[b*L_+tt] = (float)bidx;
    }
}

// ---------------- the single persistent kernel ----------------
__global__ void __launch_bounds__(NT_, 1) seq_kernel(
    const float* __restrict__ inputs, const int* __restrict__ lengths,
    const int* __restrict__ targets,
    const float* __restrict__ W_in, const float* __restrict__ b_in,
    const float* __restrict__ enc_Wi, const float* __restrict__ enc_Wh,
    const float* __restrict__ enc_bi, const float* __restrict__ enc_bh,
    const float* __restrict__ dec_Wi, const float* __restrict__ dec_Wh,
    const float* __restrict__ dec_bi, const float* __restrict__ dec_bh,
    const float* __restrict__ s2s_Wq, const float* __restrict__ s2s_Wk,
    const float* __restrict__ s2s_v,
    const float* __restrict__ W_out, const float* __restrict__ b_out,
    const float* __restrict__ ptr_Wq, const float* __restrict__ ptr_Wk,
    const float* __restrict__ ptr_v,
    float* __restrict__ out_logits, float* __restrict__ out_preds)
{
    extern __shared__ char sm_raw[];
    const int tid  = threadIdx.x;
    const int bid  = blockIdx.x;
    const int u    = tid >> 7;
    const int t128 = tid & 127;
    const int slot = bid + u * NB;
    const int gtid = bid * NT_ + tid;

    ull   (*Asd)[32][32] = (ull(*)[32][32])(sm_raw + SMEM_ASD + u * 16384);
    float (*Bs)[32][68]  = (float(*)[32][68])(sm_raw + SMEM_BS + u * 17408);
    float* scr           = (float*)(sm_raw + SMEM_SCR + u * 2304);
    const unsigned bs_u32 = smem_u32(sm_raw + SMEM_BS + u * 17408);

    float* ghb[4]  = { g_gh, g_gh2, g_gh3, g_gh4 };
    float* gicb[4] = { g_gic, g_gic2, g_gic3, g_gic4 };
    float* qb[4]   = { g_q, g_q2, g_q3, g_q4 };
    float* dob[4]  = { g_dout, g_dout2, g_dout3, g_dout4 };

    // ---- phase 0: dense, masks, zero h, weight transposes ----
    for (int i = gtid; i < B_*L_*D_; i += GSTRIDE) {
        int m = i >> 8, d = i & 255;
        g_dense[i] = inputs[m*2]*W_in[d*2] + inputs[m*2+1]*W_in[d*2+1] + b_in[d];
    }
    for (int i = gtid; i < B_*L_; i += GSTRIDE) {
        int b = i >> 6, l = i & 63;
        int fo = L_;
        for (int s = 0; s < L_; s++) if (targets[b*L_+s] == l) { fo = s; break; }
        g_fo[b*L_+l] = fo;
        g_idx[l*B_+b] = (l == 0) ? 0 : targets[b*L_ + l - 1];
    }
    for (int i = gtid; i < B_*H_; i += GSTRIDE) g_h[i] = 0.f;
    for (int i = gtid; i < H_*G3H_; i += GSTRIDE) {
        int k = i / G3H_, n = i - k*G3H_;
        g_encWhT[i]    = enc_Wh[n*H_ + k];
        g_decWhT[i]    = dec_Wh[n*H_ + k];
        g_decWiCtxT[i] = dec_Wi[n*(H_+D_) + k];
    }
    for (int i = gtid; i < D_*G3H_; i += GSTRIDE) {
        int k = i / G3H_, n = i - k*G3H_;
        g_encWiT[i]  = enc_Wi[n*D_ + k];
        g_decWiXT[i] = dec_Wi[n*(H_+D_) + H_ + k];
    }
    for (int i = gtid; i < H_*D_; i += GSTRIDE) {
        int k = i >> 8, n = i & 255;
        g_WoutT[i] = W_out[n*H_ + k];
    }
    gsync();

    // ---- precompute: enc_gi (6144), decx_gi (6144), ptr_keys (1024), K=256 ----
    for (int j = slot; j < 13312; j += NSLOT) {
        if (j < 6144) {
            int mi = j / 24, ni = j - mi*24;
            tileg<1>(g_dense,0,0,0, D_, g_encWiT, G3H_, 0, g_enc_gi, G3H_,
                     0, D_, mi*32, ni*64, t128, u, Asd, Bs, bs_u32);
        } else if (j < 12288) {
            int j2 = j - 6144; int mi = j2 / 24, ni = j2 - mi*24;
            tileg<1>(g_dense,0,0,0, D_, g_decWiXT, G3H_, 0, g_decx_gi, G3H_,
                     0, D_, mi*32, ni*64, t128, u, Asd, Bs, bs_u32);
        } else {
            int j2 = j - 12288; int mi = j2 >> 2, ni = j2 & 3;
            tileg<1>(g_dense,0,0,0, D_, ptr_Wk, AP_, 0, g_ptr_keys, AP_,
                     0, D_, mi*32, ni*64, t128, u, Asd, Bs, bs_u32);
        }
    }
    gsync();

    // ---- encoder: gh K-split x4 (384 jobs) per step ----
    for (int t = 0; t < L_; t++) {
        for (int j = slot; j < 384; j += NSLOT) {
            int tile = j >> 2, ks = j & 3;
            int mi = tile / 24, ni = tile - mi*24;
            tileg<1>(g_h,0,0,0, H_, g_encWhT, G3H_, 0, ghb[ks], G3H_,
                     ks*128, ks*128+128, mi*32, ni*64, t128, u, Asd, Bs, bs_u32);
        }
        gsync();
        for (int i = gtid; i < B_*H_; i += GSTRIDE) {
            int b = i >> 9, jj = i & 511;
            const float* gi = g_enc_gi + (b*L_+t)*G3H_;
            int base = b*G3H_;
            float s0 = g_gh[base+jj]      + g_gh2[base+jj]      + g_gh3[base+jj]      + g_gh4[base+jj];
            float s1 = g_gh[base+jj+H_]   + g_gh2[base+jj+H_]   + g_gh3[base+jj+H_]   + g_gh4[base+jj+H_];
            float s2 = g_gh[base+jj+2*H_] + g_gh2[base+jj+2*H_] + g_gh3[base+jj+2*H_] + g_gh4[base+jj+2*H_];
            float r  = sigax(gi[jj]       + enc_bi[jj]       + s0 + enc_bh[jj]);
            float z  = sigax(gi[jj+H_]    + enc_bi[jj+H_]    + s1 + enc_bh[jj+H_]);
            float n  = tanhax(gi[jj+2*H_] + enc_bi[jj+2*H_]  + r*(s2 + enc_bh[jj+2*H_]));
            float h  = g_h[i];
            float hn = (1.f - z)*n + z*h;
            g_h[i] = hn;
            g_enc_out[(b*L_+t)*H_+jj] = (t < lengths[b]) ? hn : 0.f;
        }
        gsync();
    }

    // ---- enc_keys (2048, K=512) + hidden0 gather (8) ----
    for (int j = slot; j < 2056; j += NSLOT) {
        if (j < 2048) {
            int mi = j >> 3, ni = j & 7;
            tileg<1>(g_enc_out,0,0,0, H_, s2s_Wk, AS_, 0, g_enc_keys, AS_,
                     0, H_, mi*32, ni*64, t128, u, Asd, Bs, bs_u32);
        } else {
            int jb = j - 2048;
            for (int e = t128; e < 8192; e += 128) {
                int i = jb*8192 + e;
                int b = i >> 9, jj = i & 511;
                g_h[i] = g_enc_out[(b*L_ + lengths[b]-1)*H_ + jj];
            }
        }
    }
    gsync();

    // ---- decoder ----
    for (int t = 0; t <= L_; t++) {
        const int tp = t - 1;
        // P1: gh x4 (384) + q x4 (128) — all K=128 spans
        {
            int ng = (t < L_) ? 384 : 0, nq = (t < L_) ? 128 : 0;
            for (int j = slot; j < ng + nq; j += NSLOT) {
                if (j < ng) {
                    int tile = j >> 2, ks = j & 3;
                    int mi = tile / 24, ni = tile - mi*24;
                    tileg<1>(g_h,0,0,0, H_, g_decWhT, G3H_, 0, ghb[ks], G3H_,
                             ks*128, ks*128+128, mi*32, ni*64, t128, u, Asd, Bs, bs_u32);
                } else {
                    int j2 = j - ng; int tile = j2 >> 2, ks = j2 & 3;
                    int mi = tile >> 3, ni = tile & 7;
                    tileg<1>(g_h,0,0,0, H_, s2s_Wq, AS_, 0, qb[ks], AS_,
                             ks*128, ks*128+128, mi*32, ni*64, t128, u, Asd, Bs, bs_u32);
                }
            }
            gsync();
        }
        // P2: s2s attention_t (128) + dout_{t-1} x4 (64)
        {
            int na = (t < L_) ? 128 : 0, nd = (t > 0) ? 64 : 0;
            for (int j = slot; j < na + nd; j += NSLOT) {
                if (j < na) {
                    attn_s2s_job(j, t, t128, u, scr, lengths, s2s_v);
                } else {
                    int j2 = j - na; int tile = j2 >> 2, ks = j2 & 3;
                    int mi = tile >> 2, ni = tile & 3;
                    tileg<1>(g_h,0,0,0, H_, g_WoutT, D_, (ks==0)?b_out:0, dob[ks], D_,
                             ks*128, ks*128+128, mi*32, ni*64, t128, u, Asd, Bs, bs_u32);
                }
            }
            gsync();
        }
        // P3: gic x4 (384) + pq x2 (32, A = sum of 4 dout parts)
        {
            int ng = (t < L_) ? 384 : 0, np = (t > 0) ? 32 : 0;
            for (int j = slot; j < ng + np; j += NSLOT) {
                if (j < ng) {
                    int tile = j >> 2, ks = j & 3;
                    int mi = tile / 24, ni = tile - mi*24;
                    tileg<1>(g_ctx,0,0,0, H_, g_decWiCtxT, G3H_, 0, gicb[ks], G3H_,
                             ks*128, ks*128+128, mi*32, ni*64, t128, u, Asd, Bs, bs_u32);
                } else {
                    int j2 = j - ng; int tile = j2 >> 1, ks = j2 & 1;
                    int mi = tile >> 2, ni = tile & 3;
                    tileg<4>(g_dout, g_dout2, g_dout3, g_dout4, D_, ptr_Wq, AP_, 0,
                             ks ? g_pq2 : g_pq, AP_,
                             ks*128, ks*128+128, mi*32, ni*64, t128, u, Asd, Bs, bs_u32);
                }
            }
            gsync();
        }
        // P4: ptr attention_{t-1} (units 0..127) + GRU pointwise (units 128..511)
        {
            if (t > 0 && slot < 128) {
                ptr_attn_job(slot, tp, t128, u, scr, lengths, ptr_v, out_logits, out_preds);
            } else if (t < L_ && slot >= 128) {
                for (int i = (slot-128)*128 + t128; i < B_*H_; i += 384*128) {
                    int b = i >> 9, jj = i & 511;
                    int ix = g_idx[t*B_ + b];
                    const float* gx = g_decx_gi + (b*L_+ix)*G3H_;
                    int base = b*G3H_;
                    float c0 = g_gic[base+jj]      + g_gic2[base+jj]      + g_gic3[base+jj]      + g_gic4[base+jj];
                    float c1 = g_gic[base+jj+H_]   + g_gic2[base+jj+H_]   + g_gic3[base+jj+H_]   + g_gic4[base+jj+H_];
                    float c2 = g_gic[base+jj+2*H_] + g_gic2[base+jj+2*H_] + g_gic3[base+jj+2*H_] + g_gic4[base+jj+2*H_];
                    float h0 = g_gh[base+jj]       + g_gh2[base+jj]       + g_gh3[base+jj]       + g_gh4[base+jj];
                    float h1 = g_gh[base+jj+H_]    + g_gh2[base+jj+H_]    + g_gh3[base+jj+H_]    + g_gh4[base+jj+H_];
                    float h2 = g_gh[base+jj+2*H_]  + g_gh2[base+jj+2*H_]  + g_gh3[base+jj+2*H_]  + g_gh4[base+jj+2*H_];
                    float r = sigax(gx[jj]       + c0 + dec_bi[jj]       + h0 + dec_bh[jj]);
                    float z = sigax(gx[jj+H_]    + c1 + dec_bi[jj+H_]    + h1 + dec_bh[jj+H_]);
                    float n = tanhax(gx[jj+2*H_] + c2 + dec_bi[jj+2*H_]  + r*(h2 + dec_bh[jj+2*H_]));
                    float h = g_h[i];
                    g_h[i] = (1.f - z)*n + z*h;
                }
            }
            gsync();
        }
    }
}

// ---------------- host ----------------
extern "C" void kernel_launch(void* const* d_in, const int* in_sizes, int n_in,
                              void* d_out, int out_size)
{
    const float* inputs  = (const float*)d_in[0];
    const int*   lengths = (const int*)  d_in[1];
    const int*   targets = (const int*)  d_in[2];
    const float* W_in    = (const float*)d_in[3];
    const float* b_in    = (const float*)d_in[4];
    const float* enc_Wi  = (const float*)d_in[5];
    const float* enc_Wh  = (const float*)d_in[6];
    const float* enc_bi  = (const float*)d_in[7];
    const float* enc_bh  = (const float*)d_in[8];
    const float* dec_Wi  = (const float*)d_in[9];
    const float* dec_Wh  = (const float*)d_in[10];
    const float* dec_bi  = (const float*)d_in[11];
    const float* dec_bh  = (const float*)d_in[12];
    const float* s2s_Wq  = (const float*)d_in[13];
    const float* s2s_Wk  = (const float*)d_in[14];
    const float* s2s_v   = (const float*)d_in[15];
    const float* W_out   = (const float*)d_in[16];
    const float* b_out   = (const float*)d_in[17];
    const float* ptr_Wq  = (const float*)d_in[18];
    const float* ptr_Wk  = (const float*)d_in[19];
    const float* ptr_v   = (const float*)d_in[20];

    float* out = (float*)d_out;
    float* out_logits = out;
    float* out_preds  = (out_size >= B_*L_*L_ + B_*L_) ? (out + B_*L_*L_) : nullptr;

    cudaFuncSetAttribute(seq_kernel, cudaFuncAttributeMaxDynamicSharedMemorySize, SMEM_TOTAL);

    seq_kernel<<<NB, NT_, SMEM_TOTAL>>>(inputs, lengths, targets, W_in, b_in,
                            enc_Wi, enc_Wh, enc_bi, enc_bh,
                            dec_Wi, dec_Wh, dec_bi, dec_bh,
                            s2s_Wq, s2s_Wk, s2s_v, W_out, b_out,
                            ptr_Wq, ptr_Wk, ptr_v,
                            out_logits, out_preds);
}

// round 15
// speedup vs baseline: 1.2416x; 1.2416x over previous
#include <cuda_runtime.h>
#include <math.h>

#define B_   128
#define L_   64
#define D_   256
#define H_   512
#define AS_  512
#define AP_  256
#define G3H_ 1536
#define NEGV (-1.0e9f)
#define NB   128
#define NT_  512
#define NU   4
#define NSLOT (NB*NU)
#define GSTRIDE (NB*NT_)

// smem per unit: Abuf 2*16*32 ull = 8192B, Bbuf 2*16*68 f = 8704B; scr 576 f per unit
#define SMEM_ASD   0
#define SMEM_BS    32768
#define SMEM_SCR   67584
#define SMEM_TOTAL 76800

// ---------------- scratch ----------------
__device__ float g_dense   [B_*L_*D_];
__device__ float g_enc_gi  [B_*L_*G3H_];
__device__ float g_decx_gi [B_*L_*G3H_];
__device__ float g_enc_out [B_*L_*H_];
__device__ float g_enc_keys[B_*L_*AS_];
__device__ float g_ptr_keys[B_*L_*AP_];
__device__ float g_h    [B_*H_];
__device__ float g_gh   [B_*G3H_];
__device__ float g_gh2  [B_*G3H_];
__device__ float g_gh3  [B_*G3H_];
__device__ float g_gh4  [B_*G3H_];
__device__ float g_gic  [B_*G3H_];
__device__ float g_gic2 [B_*G3H_];
__device__ float g_gic3 [B_*G3H_];
__device__ float g_gic4 [B_*G3H_];
__device__ float g_ctx  [B_*H_];
__device__ float g_q    [B_*AS_];
__device__ float g_q2   [B_*AS_];
__device__ float g_q3   [B_*AS_];
__device__ float g_q4   [B_*AS_];
__device__ float g_dout [B_*D_];
__device__ float g_dout2[B_*D_];
__device__ float g_dout3[B_*D_];
__device__ float g_dout4[B_*D_];
__device__ float g_pq   [B_*AP_];
__device__ float g_pq2  [B_*AP_];
// transposed (k-major) weight copies
__device__ float g_encWiT   [D_*G3H_];
__device__ float g_decWiXT  [D_*G3H_];
__device__ float g_encWhT   [H_*G3H_];
__device__ float g_decWhT   [H_*G3H_];
__device__ float g_decWiCtxT[H_*G3H_];
__device__ float g_WoutT    [H_*D_];
__device__ int   g_idx  [L_*B_];
__device__ int   g_fo   [B_*L_];
__device__ unsigned long long g_cnt;

typedef unsigned long long ull;
__device__ __forceinline__ ull pk2(float x, float y) {
    ull r; asm("mov.b64 %0, {%1, %2};" : "=l"(r) : "f"(x), "f"(y)); return r;
}
__device__ __forceinline__ void upk2(ull v, float& x, float& y) {
    asm("mov.b64 {%0, %1}, %2;" : "=f"(x), "=f"(y) : "l"(v));
}
__device__ __forceinline__ ull fma2(ull a, ull b, ull c) {
    ull d; asm("fma.rn.f32x2 %0, %1, %2, %3;" : "=l"(d) : "l"(a), "l"(b), "l"(c));
    return d;
}
__device__ __forceinline__ float tanhax(float x) {
    float y; asm("tanh.approx.f32 %0, %1;" : "=f"(y) : "f"(x)); return y;
}
__device__ __forceinline__ float ex2ax(float x) {
    float y; asm("ex2.approx.f32 %0, %1;" : "=f"(y) : "f"(x)); return y;
}
__device__ __forceinline__ float expax(float x) { return ex2ax(x * 1.4426950408889634f); }
__device__ __forceinline__ float sigax(float x) { return 0.5f * tanhax(0.5f * x) + 0.5f; }

__device__ __forceinline__ void bar_u(int u) {
    asm volatile("bar.sync %0, 128;" :: "r"(1 + u) : "memory");
}
__device__ __forceinline__ void bar_384() {
    asm volatile("bar.sync 5, 384;" ::: "memory");
}
__device__ __forceinline__ void cp16(unsigned dst, const float* src) {
    asm volatile("cp.async.cg.shared.global [%0], [%1], 16;" :: "r"(dst), "l"(src) : "memory");
}
__device__ __forceinline__ void cp_commit() {
    asm volatile("cp.async.commit_group;" ::: "memory");
}
__device__ __forceinline__ void cp_wait0() {
    asm volatile("cp.async.wait_group 0;" ::: "memory");
}
__device__ __forceinline__ unsigned smem_u32(const void* p) {
    unsigned a;
    asm("{ .reg .u64 t; cvta.to.shared.u64 t, %1; cvt.u32.u64 %0, t; }" : "=r"(a) : "l"(p));
    return a;
}

__device__ __forceinline__ void gsync() {
    __syncthreads();
    if (threadIdx.x == 0) {
        ull* p = &g_cnt;
        ull old;
        asm volatile("atom.add.release.gpu.u64 %0, [%1], %2;"
                     : "=l"(old) : "l"(p), "l"(1ULL) : "memory");
        ull target = (old - (old & (ull)(NB - 1))) + NB;
        ull cur;
        do {
            asm volatile("ld.acquire.gpu.u64 %0, [%1];" : "=l"(cur) : "l"(p) : "memory");
        } while (cur < target);
    }
    __syncthreads();
}

// ---------------- cp.async double-buffered 32x64 tile GEMM, BK=16 ----------------
// C[m0:+32,n0:+64] = (sum of NA A-arrays)[m0:+32, kb:ke] * B (+bias)
// B layout (k-major): B(k,n) = Bm[k*ldb + n]. One bar.sync per 16-k slice.
template<int NA>
__device__ __forceinline__ void tileg(
    const float* __restrict__ A0, const float* __restrict__ A1,
    const float* __restrict__ A2p, const float* __restrict__ A3p, int lda,
    const float* __restrict__ Bm, int ldb,
    const float* __restrict__ bias,
    float* __restrict__ C, int ldc, int kb, int ke,
    int m0, int n0, int t, int u,
    ull (*Asd)[16][32], float (*Bs)[16][68], unsigned bs_u32)
{
    const int ar = t >> 2, ac = t & 3;
    const int tr4 = (t >> 4) << 2;
    const int tc4 = (t & 15) << 2;
    const int arow = (m0 + ar) * lda;
    const int kk0 = t >> 4,        q0 = t & 15;
    const int kk1 = (t + 128) >> 4, q1 = (t + 128) & 15;
    const unsigned bdst0 = bs_u32 + kk0 * 272 + q0 * 16;
    const unsigned bdst1 = bs_u32 + kk1 * 272 + q1 * 16;

    ull acc00=0,acc01=0,acc10=0,acc11=0,acc20=0,acc21=0,acc30=0,acc31=0;
    float4 va;

    auto ldA = [&](int k0) {
        float4 v = *(const float4*)(A0 + arow + k0 + ac*4);
        if (NA > 1) {
            float4 x = *(const float4*)(A1 + arow + k0 + ac*4);
            v.x+=x.x; v.y+=x.y; v.z+=x.z; v.w+=x.w;
        }
        if (NA > 2) {
            float4 x = *(const float4*)(A2p + arow + k0 + ac*4);
            v.x+=x.x; v.y+=x.y; v.z+=x.z; v.w+=x.w;
            x = *(const float4*)(A3p + arow + k0 + ac*4);
            v.x+=x.x; v.y+=x.y; v.z+=x.z; v.w+=x.w;
        }
        return v;
    };
    auto cpB = [&](int k0, int p) {
        cp16(bdst0 + p*4352, Bm + (k0 + kk0)*ldb + n0 + q0*4);
        cp16(bdst1 + p*4352, Bm + (k0 + kk1)*ldb + n0 + q1*4);
        cp_commit();
    };

    const int nit = (ke - kb) >> 4;
    va = ldA(kb);
    cpB(kb, 0);
    for (int it = 0; it < nit; it++) {
        const int p = it & 1;
        Asd[p][ac*4+0][ar] = pk2(va.x, va.x);
        Asd[p][ac*4+1][ar] = pk2(va.y, va.y);
        Asd[p][ac*4+2][ar] = pk2(va.z, va.z);
        Asd[p][ac*4+3][ar] = pk2(va.w, va.w);
        cp_wait0();
        bar_u(u);
        if (it + 1 < nit) {
            va = ldA(kb + (it+1)*16);
            cpB(kb + (it+1)*16, 1 - p);
        }
#pragma unroll
        for (int kk = 0; kk < 16; kk++) {
            const ull* ap = &Asd[p][kk][tr4];
            ull a0 = ap[0], a1 = ap[1], a2 = ap[2], a3 = ap[3];
            ull b01 = *(const ull*)&Bs[p][kk][tc4];
            ull b23 = *(const ull*)&Bs[p][kk][tc4+2];
            acc00 = fma2(a0, b01, acc00); acc01 = fma2(a0, b23, acc01);
            acc10 = fma2(a1, b01, acc10); acc11 = fma2(a1, b23, acc11);
            acc20 = fma2(a2, b01, acc20); acc21 = fma2(a2, b23, acc21);
            acc30 = fma2(a3, b01, acc30); acc31 = fma2(a3, b23, acc31);
        }
    }
    bar_u(u);

    float bx0=0.f, bx1=0.f, bx2=0.f, bx3=0.f;
    if (bias) { bx0=bias[n0+tc4]; bx1=bias[n0+tc4+1]; bx2=bias[n0+tc4+2]; bx3=bias[n0+tc4+3]; }
    ull accs[4][2] = {{acc00,acc01},{acc10,acc11},{acc20,acc21},{acc30,acc31}};
#pragma unroll
    for (int i = 0; i < 4; i++) {
        float x0,x1,x2,x3;
        upk2(accs[i][0], x0, x1); upk2(accs[i][1], x2, x3);
        float4 o; o.x=x0+bx0; o.y=x1+bx1; o.z=x2+bx2; o.w=x3+bx3;
        *(float4*)(C + (m0 + tr4 + i)*ldc + n0 + tc4) = o;
    }
}

// ---------------- s2s attention: 384-thread job (units 0-2 of one block) ----------------
__device__ __forceinline__ void attn_s2s_384(
    int b, int t, int t384, float* scr,
    const int* __restrict__ lengths, const float* __restrict__ v)
{
    const int w = t384 >> 5, lane = t384 & 31;
    const int len = lengths[b];
    float* qs = scr + 64;
    for (int a = t384; a < AS_; a += 384)
        qs[a] = g_q[b*AS_+a] + g_q2[b*AS_+a] + g_q3[b*AS_+a] + g_q4[b*AS_+a];
    bar_384();
    const float* kb = g_enc_keys + b * L_ * AS_;
    for (int l = w; l < L_; l += 12) {
        const float* kp = kb + l * AS_;
        float acc = 0.f;
#pragma unroll 4
        for (int a = lane; a < AS_; a += 32)
            acc += tanhax(qs[a] + kp[a]) * v[a];
        for (int o = 16; o; o >>= 1) acc += __shfl_down_sync(0xffffffffu, acc, o);
        if (lane == 0) scr[l] = (t < len && l < len) ? acc : NEGV;
    }
    bar_384();
    if (w == 0) {
        float v0 = scr[lane], v1 = scr[lane+32];
        float m = fmaxf(v0, v1);
        for (int o = 16; o; o >>= 1) m = fmaxf(m, __shfl_xor_sync(0xffffffffu, m, o));
        float e0 = expax(v0-m), e1 = expax(v1-m);
        float s = e0 + e1;
        for (int o = 16; o; o >>= 1) s += __shfl_xor_sync(0xffffffffu, s, o);
        float inv = 1.f / s;
        scr[lane] = e0*inv; scr[lane+32] = e1*inv;
    }
    bar_384();
    for (int j = t384; j < H_; j += 384) {
        float c = 0.f;
#pragma unroll 8
        for (int l = 0; l < L_; l++)
            c += scr[l] * g_enc_out[(b*L_+l)*H_ + j];
        g_ctx[b*H_ + j] = c;
    }
}

// ---------------- ptr attention: 512-thread block-cooperative job ----------------
__device__ __forceinline__ void ptr_attn_512(
    int b, int tt, int tid, float* scr,
    const int* __restrict__ lengths, const float* __restrict__ pv,
    float* __restrict__ out_logits, float* __restrict__ out_preds)
{
    const int w = tid >> 5, lane = tid & 31;
    const int len = lengths[b];
    float* qs = scr + 64;
    for (int a = tid; a < AP_; a += 512)
        qs[a] = g_pq[b*AP_+a] + g_pq2[b*AP_+a];
    __syncthreads();
    const float* kb = g_ptr_keys + b * L_ * AP_;
#pragma unroll
    for (int l = w; l < L_; l += 16) {
        const float* kp = kb + l * AP_;
        float acc = 0.f;
#pragma unroll
        for (int a = lane; a < AP_; a += 32)
            acc += tanhax(qs[a] + kp[a]) * pv[a];
        for (int o = 16; o; o >>= 1) acc += __shfl_down_sync(0xffffffffu, acc, o);
        if (lane == 0) {
            bool ok = (tt < len) && (l < len) && (g_fo[b*L_+l] >= tt);
            float val = ok ? acc : NEGV;
            scr[l] = val;
            out_logits[(b*L_+tt)*L_ + l] = val;
        }
    }
    __syncthreads();
    if (w == 0 && out_preds) {
        float v0 = scr[lane], v1 = scr[lane+32];
        float bv; int bidx;
        if (v1 > v0) { bv = v1; bidx = lane+32; } else { bv = v0; bidx = lane; }
        for (int o = 16; o; o >>= 1) {
            float ov = __shfl_down_sync(0xffffffffu, bv, o);
            int   oi = __shfl_down_sync(0xffffffffu, bidx, o);
            if (ov > bv || (ov == bv && oi < bidx)) { bv = ov; bidx = oi; }
        }
        if (lane == 0) out_preds[b*L_+tt] = (float)bidx;
    }
}

// ---------------- the single persistent kernel ----------------
__global__ void __launch_bounds__(NT_, 1) seq_kernel(
    const float* __restrict__ inputs, const int* __restrict__ lengths,
    const int* __restrict__ targets,
    const float* __restrict__ W_in, const float* __restrict__ b_in,
    const float* __restrict__ enc_Wi, const float* __restrict__ enc_Wh,
    const float* __restrict__ enc_bi, const float* __restrict__ enc_bh,
    const float* __restrict__ dec_Wi, const float* __restrict__ dec_Wh,
    const float* __restrict__ dec_bi, const float* __restrict__ dec_bh,
    const float* __restrict__ s2s_Wq, const float* __restrict__ s2s_Wk,
    const float* __restrict__ s2s_v,
    const float* __restrict__ W_out, const float* __restrict__ b_out,
    const float* __restrict__ ptr_Wq, const float* __restrict__ ptr_Wk,
    const float* __restrict__ ptr_v,
    float* __restrict__ out_logits, float* __restrict__ out_preds)
{
    extern __shared__ char sm_raw[];
    const int tid  = threadIdx.x;
    const int bid  = blockIdx.x;
    const int u    = tid >> 7;
    const int t128 = tid & 127;
    const int slot = bid + u * NB;
    const int gtid = bid * NT_ + tid;

    ull   (*Asd)[16][32] = (ull(*)[16][32])(sm_raw + SMEM_ASD + u * 8192);
    float (*Bs)[16][68]  = (float(*)[16][68])(sm_raw + SMEM_BS + u * 8704);
    float* scr           = (float*)(sm_raw + SMEM_SCR + u * 576*4);
    float* scr0          = (float*)(sm_raw + SMEM_SCR);   // block-level scratch (unit 0 region)
    const unsigned bs_u32 = smem_u32(sm_raw + SMEM_BS + u * 8704);

    float* ghb[4]  = { g_gh, g_gh2, g_gh3, g_gh4 };
    float* gicb[4] = { g_gic, g_gic2, g_gic3, g_gic4 };
    float* qb[4]   = { g_q, g_q2, g_q3, g_q4 };
    float* dob[4]  = { g_dout, g_dout2, g_dout3, g_dout4 };

    // ---- phase 0: dense, masks, zero h, weight transposes ----
    for (int i = gtid; i < B_*L_*D_; i += GSTRIDE) {
        int m = i >> 8, d = i & 255;
        g_dense[i] = inputs[m*2]*W_in[d*2] + inputs[m*2+1]*W_in[d*2+1] + b_in[d];
    }
    for (int i = gtid; i < B_*L_; i += GSTRIDE) {
        int b = i >> 6, l = i & 63;
        int fo = L_;
        for (int s = 0; s < L_; s++) if (targets[b*L_+s] == l) { fo = s; break; }
        g_fo[b*L_+l] = fo;
        g_idx[l*B_+b] = (l == 0) ? 0 : targets[b*L_ + l - 1];
    }
    for (int i = gtid; i < B_*H_; i += GSTRIDE) g_h[i] = 0.f;
    for (int i = gtid; i < H_*G3H_; i += GSTRIDE) {
        int k = i / G3H_, n = i - k*G3H_;
        g_encWhT[i]    = enc_Wh[n*H_ + k];
        g_decWhT[i]    = dec_Wh[n*H_ + k];
        g_decWiCtxT[i] = dec_Wi[n*(H_+D_) + k];
    }
    for (int i = gtid; i < D_*G3H_; i += GSTRIDE) {
        int k = i / G3H_, n = i - k*G3H_;
        g_encWiT[i]  = enc_Wi[n*D_ + k];
        g_decWiXT[i] = dec_Wi[n*(H_+D_) + H_ + k];
    }
    for (int i = gtid; i < H_*D_; i += GSTRIDE) {
        int k = i >> 8, n = i & 255;
        g_WoutT[i] = W_out[n*H_ + k];
    }
    gsync();

    // ---- precompute: enc_gi (6144), decx_gi (6144), ptr_keys (1024), K=256 ----
    for (int j = slot; j < 13312; j += NSLOT) {
        if (j < 6144) {
            int mi = j / 24, ni = j - mi*24;
            tileg<1>(g_dense,0,0,0, D_, g_encWiT, G3H_, 0, g_enc_gi, G3H_,
                     0, D_, mi*32, ni*64, t128, u, Asd, Bs, bs_u32);
        } else if (j < 12288) {
            int j2 = j - 6144; int mi = j2 / 24, ni = j2 - mi*24;
            tileg<1>(g_dense,0,0,0, D_, g_decWiXT, G3H_, 0, g_decx_gi, G3H_,
                     0, D_, mi*32, ni*64, t128, u, Asd, Bs, bs_u32);
        } else {
            int j2 = j - 12288; int mi = j2 >> 2, ni = j2 & 3;
            tileg<1>(g_dense,0,0,0, D_, ptr_Wk, AP_, 0, g_ptr_keys, AP_,
                     0, D_, mi*32, ni*64, t128, u, Asd, Bs, bs_u32);
        }
    }
    gsync();

    // ---- encoder: gh K-split x4 (384 jobs) per step ----
    for (int t = 0; t < L_; t++) {
        for (int j = slot; j < 384; j += NSLOT) {
            int tile = j >> 2, ks = j & 3;
            int mi = tile / 24, ni = tile - mi*24;
            tileg<1>(g_h,0,0,0, H_, g_encWhT, G3H_, 0, ghb[ks], G3H_,
                     ks*128, ks*128+128, mi*32, ni*64, t128, u, Asd, Bs, bs_u32);
        }
        gsync();
        for (int i = gtid; i < B_*H_; i += GSTRIDE) {
            int b = i >> 9, jj = i & 511;
            const float* gi = g_enc_gi + (b*L_+t)*G3H_;
            int base = b*G3H_;
            float s0 = g_gh[base+jj]      + g_gh2[base+jj]      + g_gh3[base+jj]      + g_gh4[base+jj];
            float s1 = g_gh[base+jj+H_]   + g_gh2[base+jj+H_]   + g_gh3[base+jj+H_]   + g_gh4[base+jj+H_];
            float s2 = g_gh[base+jj+2*H_] + g_gh2[base+jj+2*H_] + g_gh3[base+jj+2*H_] + g_gh4[base+jj+2*H_];
            float r  = sigax(gi[jj]       + enc_bi[jj]       + s0 + enc_bh[jj]);
            float z  = sigax(gi[jj+H_]    + enc_bi[jj+H_]    + s1 + enc_bh[jj+H_]);
            float n  = tanhax(gi[jj+2*H_] + enc_bi[jj+2*H_]  + r*(s2 + enc_bh[jj+2*H_]));
            float h  = g_h[i];
            float hn = (1.f - z)*n + z*h;
            g_h[i] = hn;
            g_enc_out[(b*L_+t)*H_+jj] = (t < lengths[b]) ? hn : 0.f;
        }
        gsync();
    }

    // ---- enc_keys (2048, K=512) + hidden0 gather (8) ----
    for (int j = slot; j < 2056; j += NSLOT) {
        if (j < 2048) {
            int mi = j >> 3, ni = j & 7;
            tileg<1>(g_enc_out,0,0,0, H_, s2s_Wk, AS_, 0, g_enc_keys, AS_,
                     0, H_, mi*32, ni*64, t128, u, Asd, Bs, bs_u32);
        } else {
            int jb = j - 2048;
            for (int e = t128; e < 8192; e += 128) {
                int i = jb*8192 + e;
                int b = i >> 9, jj = i & 511;
                g_h[i] = g_enc_out[(b*L_ + lengths[b]-1)*H_ + jj];
            }
        }
    }
    gsync();

    // ---- decoder ----
    for (int t = 0; t <= L_; t++) {
        const int tp = t - 1;
        // P1: gh x4 (384) + q x4 (128) — all K=128 spans
        {
            int ng = (t < L_) ? 384 : 0, nq = (t < L_) ? 128 : 0;
            for (int j = slot; j < ng + nq; j += NSLOT) {
                if (j < ng) {
                    int tile = j >> 2, ks = j & 3;
                    int mi = tile / 24, ni = tile - mi*24;
                    tileg<1>(g_h,0,0,0, H_, g_decWhT, G3H_, 0, ghb[ks], G3H_,
                             ks*128, ks*128+128, mi*32, ni*64, t128, u, Asd, Bs, bs_u32);
                } else {
                    int j2 = j - ng; int tile = j2 >> 2, ks = j2 & 3;
                    int mi = tile >> 3, ni = tile & 7;
                    tileg<1>(g_h,0,0,0, H_, s2s_Wq, AS_, 0, qb[ks], AS_,
                             ks*128, ks*128+128, mi*32, ni*64, t128, u, Asd, Bs, bs_u32);
                }
            }
            gsync();
        }
        // P2: s2s attention_t on units 0-2 (batch = bid) + dout_{t-1} x4 on unit 3 of blocks 0-63
        {
            if (t < L_ && u < 3) {
                attn_s2s_384(bid, t, tid, scr0, lengths, s2s_v);
            } else if (t > 0 && u == 3 && bid < 64) {
                int tile = bid >> 2, ks = bid & 3;
                int mi = tile >> 2, ni = tile & 3;
                tileg<1>(g_h,0,0,0, H_, g_WoutT, D_, (ks==0)?b_out:0, dob[ks], D_,
                         ks*128, ks*128+128, mi*32, ni*64, t128, u, Asd, Bs, bs_u32);
            }
            gsync();
        }
        // P3: gic x4 (384) + pq x2 (32, A = sum of 4 dout parts)
        {
            int ng = (t < L_) ? 384 : 0, np = (t > 0) ? 32 : 0;
            for (int j = slot; j < ng + np; j += NSLOT) {
                if (j < ng) {
                    int tile = j >> 2, ks = j & 3;
                    int mi = tile / 24, ni = tile - mi*24;
                    tileg<1>(g_ctx,0,0,0, H_, g_decWiCtxT, G3H_, 0, gicb[ks], G3H_,
                             ks*128, ks*128+128, mi*32, ni*64, t128, u, Asd, Bs, bs_u32);
                } else {
                    int j2 = j - ng; int tile = j2 >> 1, ks = j2 & 1;
                    int mi = tile >> 2, ni = tile & 3;
                    tileg<4>(g_dout, g_dout2, g_dout3, g_dout4, D_, ptr_Wq, AP_, 0,
                             ks ? g_pq2 : g_pq, AP_,
                             ks*128, ks*128+128, mi*32, ni*64, t128, u, Asd, Bs, bs_u32);
                }
            }
            gsync();
        }
        // P4: ptr attention_{t-1} block-cooperative (batch = bid) then GRU pointwise (full grid)
        {
            if (t > 0) {
                ptr_attn_512(bid, tp, tid, scr0, lengths, ptr_v, out_logits, out_preds);
            }
            if (t < L_) {
                if (t > 0) __syncthreads();
                for (int i = gtid; i < B_*H_; i += GSTRIDE) {
                    int b = i >> 9, jj = i & 511;
                    int ix = g_idx[t*B_ + b];
                    const float* gx = g_decx_gi + (b*L_+ix)*G3H_;
                    int base = b*G3H_;
                    float c0 = g_gic[base+jj]      + g_gic2[base+jj]      + g_gic3[base+jj]      + g_gic4[base+jj];
                    float c1 = g_gic[base+jj+H_]   + g_gic2[base+jj+H_]   + g_gic3[base+jj+H_]   + g_gic4[base+jj+H_];
                    float c2 = g_gic[base+jj+2*H_] + g_gic2[base+jj+2*H_] + g_gic3[base+jj+2*H_] + g_gic4[base+jj+2*H_];
                    float h0 = g_gh[base+jj]       + g_gh2[base+jj]       + g_gh3[base+jj]       + g_gh4[base+jj];
                    float h1 = g_gh[base+jj+H_]    + g_gh2[base+jj+H_]    + g_gh3[base+jj+H_]    + g_gh4[base+jj+H_];
                    float h2 = g_gh[base+jj+2*H_]  + g_gh2[base+jj+2*H_]  + g_gh3[base+jj+2*H_]  + g_gh4[base+jj+2*H_];
                    float r = sigax(gx[jj]       + c0 + dec_bi[jj]       + h0 + dec_bh[jj]);
                    float z = sigax(gx[jj+H_]    + c1 + dec_bi[jj+H_]    + h1 + dec_bh[jj+H_]);
                    float n = tanhax(gx[jj+2*H_] + c2 + dec_bi[jj+2*H_]  + r*(h2 + dec_bh[jj+2*H_]));
                    float h = g_h[i];
                    g_h[i] = (1.f - z)*n + z*h;
                }
            }
            gsync();
        }
    }
}

// ---------------- host ----------------
extern "C" void kernel_launch(void* const* d_in, const int* in_sizes, int n_in,
                              void* d_out, int out_size)
{
    const float* inputs  = (const float*)d_in[0];
    const int*   lengths = (const int*)  d_in[1];
    const int*   targets = (const int*)  d_in[2];
    const float* W_in    = (const float*)d_in[3];
    const float* b_in    = (const float*)d_in[4];
    const float* enc_Wi  = (const float*)d_in[5];
    const float* enc_Wh  = (const float*)d_in[6];
    const float* enc_bi  = (const float*)d_in[7];
    const float* enc_bh  = (const float*)d_in[8];
    const float* dec_Wi  = (const float*)d_in[9];
    const float* dec_Wh  = (const float*)d_in[10];
    const float* dec_bi  = (const float*)d_in[11];
    const float* dec_bh  = (const float*)d_in[12];
    const float* s2s_Wq  = (const float*)d_in[13];
    const float* s2s_Wk  = (const float*)d_in[14];
    const float* s2s_v   = (const float*)d_in[15];
    const float* W_out   = (const float*)d_in[16];
    const float* b_out   = (const float*)d_in[17];
    const float* ptr_Wq  = (const float*)d_in[18];
    const float* ptr_Wk  = (const float*)d_in[19];
    const float* ptr_v   = (const float*)d_in[20];

    float* out = (float*)d_out;
    float* out_logits = out;
    float* out_preds  = (out_size >= B_*L_*L_ + B_*L_) ? (out + B_*L_*L_) : nullptr;

    cudaFuncSetAttribute(seq_kernel, cudaFuncAttributeMaxDynamicSharedMemorySize, SMEM_TOTAL);

    seq_kernel<<<NB, NT_, SMEM_TOTAL>>>(inputs, lengths, targets, W_in, b_in,
                            enc_Wi, enc_Wh, enc_bi, enc_bh,
                            dec_Wi, dec_Wh, dec_bi, dec_bh,
                            s2s_Wq, s2s_Wk, s2s_v, W_out, b_out,
                            ptr_Wq, ptr_Wk, ptr_v,
                            out_logits, out_preds);
}